// round 2
// baseline (speedup 1.0000x reference)
#include <cuda_runtime.h>
#include <cuda_bf16.h>
#include <math.h>
#include <stdint.h>

#define N_LEVELS   16
#define HASH_BITS  19
#define TABLE_SIZE (1u << HASH_BITS)
#define HASH_MASK  (TABLE_SIZE - 1u)

struct LevelRes {
    int res[N_LEVELS];
};

// XLA-GPU lowers f32 divide to div.full.f32 (fast, ~2ulp, NOT correctly
// rounded). The hash trunc amplifies 1-ulp differences into wrong table
// indices, so we must reproduce the exact same division instruction.
__device__ __forceinline__ float div_full(float a, float b) {
    float r;
    asm("div.full.f32 %0, %1, %2;" : "=f"(r) : "f"(a), "f"(b));
    return r;
}

__global__ void __launch_bounds__(256)
hash_encoding_kernel(const float* __restrict__ x,
                     const float* __restrict__ tables,
                     float* __restrict__ out,
                     LevelRes lp,
                     int n_points)
{
    int tid = blockIdx.x * blockDim.x + threadIdx.x;
    int n     = tid >> 4;        // point index
    int level = tid & 15;        // level index (fastest within warp)
    if (n >= n_points) return;

    // Load & clip point (16 threads share a point -> L1 broadcast)
    float xv0 = fminf(fmaxf(__ldg(&x[(size_t)n * 3 + 0]), -1.0f), 1.0f);
    float xv1 = fminf(fmaxf(__ldg(&x[(size_t)n * 3 + 1]), -1.0f), 1.0f);
    float xv2 = fminf(fmaxf(__ldg(&x[(size_t)n * 3 + 2]), -1.0f), 1.0f);

    const int   res  = lp.res[level];
    const float fres = (float)res;

    const unsigned primes[3] = {1u, 2654435761u, 805459861u};
    float xs[3] = {xv0, xv1, xv2};

    unsigned hpart[3][2];
    float    w[3][2];

#pragma unroll
    for (int d = 0; d < 3; d++) {
        float coord = xs[d] * fres;
        float cf    = floorf(coord);
        float lc    = coord - cf;
        int   ci    = (int)cf;
        w[d][0] = 1.0f - lc;
        w[d][1] = lc;
#pragma unroll
        for (int o = 0; o < 2; o++) {
            int c = (ci + o) % res;          // floor-mod like jnp: fix sign
            if (c < 0) c += res;
            // corners_f = c / res, matching XLA's div.full.f32 exactly
            float cfrac = div_full((float)c, fres);
            // q = trunc((cfrac + 1) * 0.5 * 2^18)
            // Both multiplies are exact power-of-2 scalings: rounding happens
            // once, on the same grid, under any association/FMA form.
            float qf = __fmul_rn(__fmul_rn(__fadd_rn(cfrac, 1.0f), 0.5f),
                                 262144.0f);
            unsigned q = (unsigned)qf;        // positive -> trunc == astype
            hpart[d][o] = q * primes[d];      // uint32 wrap OK: 2^19 | 2^32
        }
    }

    const float2* __restrict__ tab =
        reinterpret_cast<const float2*>(tables) + (size_t)level * TABLE_SIZE;

    // Compute all 8 hashes, then issue all 8 gathers (MLP=8)
    unsigned h[8];
#pragma unroll
    for (int k = 0; k < 8; k++) {
        int o0 = (k >> 2) & 1, o1 = (k >> 1) & 1, o2 = k & 1;
        h[k] = (hpart[0][o0] + hpart[1][o1] + hpart[2][o2]) & HASH_MASK;
    }

    float2 f[8];
#pragma unroll
    for (int k = 0; k < 8; k++) {
        f[k] = __ldg(tab + h[k]);
    }

    float acc0 = 0.0f, acc1 = 0.0f;
#pragma unroll
    for (int k = 0; k < 8; k++) {
        int o0 = (k >> 2) & 1, o1 = (k >> 1) & 1, o2 = k & 1;
        float wk = w[0][o0] * w[1][o1] * w[2][o2];
        acc0 += wk * f[k].x;
        acc1 += wk * f[k].y;
    }

    // out[n, level*2 .. level*2+1] -- coalesced float2 store (128B per warp)
    reinterpret_cast<float2*>(out)[(size_t)n * N_LEVELS + level] =
        make_float2(acc0, acc1);
}

extern "C" void kernel_launch(void* const* d_in, const int* in_sizes, int n_in,
                              void* d_out, int out_size)
{
    const float* x      = (const float*)d_in[0];
    const float* tables = (const float*)d_in[1];
    float*       out    = (float*)d_out;

    int n_points = in_sizes[0] / 3;

    // Replicate CPython: int(MIN_RES * (MAX_RES/MIN_RES) ** (i/(L-1)))
    // Host libm pow (same glibc as the reference container) -- values like
    // 32^(9/15) land a hair below an exact power of two in double.
    LevelRes lp;
    for (int i = 0; i < N_LEVELS; i++) {
        double r = 16.0 * pow(32.0, (double)i / 15.0);
        lp.res[i] = (int)r;
    }

    int total   = n_points * N_LEVELS;
    int threads = 256;
    int blocks  = (total + threads - 1) / threads;
    hash_encoding_kernel<<<blocks, threads>>>(x, tables, out, lp, n_points);
}

// round 3
// speedup vs baseline: 1.1374x; 1.1374x over previous
#include <cuda_runtime.h>
#include <cuda_bf16.h>
#include <math.h>
#include <stdint.h>

#define N_LEVELS   16
#define N_DENSE    10          // levels 0..9 (res <= ~128) served from dense z-paired grid
#define HASH_BITS  19
#define TABLE_SIZE (1u << HASH_BITS)
#define HASH_MASK  (TABLE_SIZE - 1u)

// Dense z-paired scratch: entry (cx,cy,cz) = {tab[h(..,cz)], tab[h(..,(cz+1)%res)]}
// Upper bound on sum(res^3) for levels 0..9 (actual ~4.10M with host-pow res).
#define DENSE_CAP  4300000
__device__ float4 g_dense[DENSE_CAP];   // ~68.8 MB static scratch (no allocation)

struct Params {
    int res[N_LEVELS];
    int dense_base[N_DENSE];      // float4 offset of each dense level in g_dense
    int fill_prefix[N_DENSE + 1]; // prefix sum of res^3 (corner counts)
};

// XLA-GPU lowers f32 divide to div.full.f32 (fast, ~2ulp, NOT correctly
// rounded). The hash trunc amplifies 1-ulp differences into wrong indices,
// so we reproduce the exact instruction.
__device__ __forceinline__ float div_full(float a, float b) {
    float r;
    asm("div.full.f32 %0, %1, %2;" : "=f"(r) : "f"(a), "f"(b));
    return r;
}

// Exact replication of the reference hash for integer corner c in [0,res)
__device__ __forceinline__ unsigned hash_part(int c, float fres, unsigned prime) {
    float cfrac = div_full((float)c, fres);
    float qf = __fmul_rn(__fmul_rn(__fadd_rn(cfrac, 1.0f), 0.5f), 262144.0f);
    unsigned q = (unsigned)qf;          // positive -> trunc == astype(int64)
    return q * prime;                    // uint32 wrap OK: 2^19 | 2^32
}

// ---------------------------------------------------------------------------
// Fill kernel: one thread per dense corner. Gathers tab[h(corner)] and writes
// it as .xy of entry (cz) and .zw of entry (cz-1 mod res). Pure copy: values
// are bit-identical to the table.
// ---------------------------------------------------------------------------
__global__ void __launch_bounds__(256)
fill_dense_kernel(const float* __restrict__ tables, Params p, int total)
{
    int tid = blockIdx.x * blockDim.x + threadIdx.x;
    if (tid >= total) return;

    // find level (<=10 entries, tiny scan)
    int level = 0;
#pragma unroll
    for (int i = 0; i < N_DENSE; i++)
        if (tid >= p.fill_prefix[i + 1]) level = i + 1;

    int r  = tid - p.fill_prefix[level];
    int res = p.res[level];
    int cz = r % res;
    int t  = r / res;
    int cy = t % res;
    int cx = t / res;

    float fres = (float)res;
    unsigned h = (hash_part(cx, fres, 1u) +
                  hash_part(cy, fres, 2654435761u) +
                  hash_part(cz, fres, 805459861u)) & HASH_MASK;

    const float2* tab = reinterpret_cast<const float2*>(tables)
                        + (size_t)level * TABLE_SIZE;
    float2 v = __ldg(tab + h);

    float4* base = g_dense + p.dense_base[level];
    int idx      = (cx * res + cy) * res + cz;
    int idx_prev = (cx * res + cy) * res + (cz == 0 ? res - 1 : cz - 1);

    // .xy of own entry, .zw of previous-z entry (handles wrap)
    reinterpret_cast<float2*>(&base[idx])[0]      = v;
    reinterpret_cast<float2*>(&base[idx_prev])[1] = v;
}

// ---------------------------------------------------------------------------
// Main kernel: thread per (point, level), level fastest within warp.
// Dense levels: 4x LDG.128 from z-paired grid. Hashed levels: 8x LDG.64.
// ---------------------------------------------------------------------------
__global__ void __launch_bounds__(256)
hash_encoding_kernel(const float* __restrict__ x,
                     const float* __restrict__ tables,
                     float* __restrict__ out,
                     Params p,
                     int n_points)
{
    int tid = blockIdx.x * blockDim.x + threadIdx.x;
    int n     = tid >> 4;
    int level = tid & 15;
    if (n >= n_points) return;

    float xv[3];
#pragma unroll
    for (int d = 0; d < 3; d++)
        xv[d] = fminf(fmaxf(__ldg(&x[(size_t)n * 3 + d]), -1.0f), 1.0f);

    const int   res  = p.res[level];
    const float fres = (float)res;

    int   c0[3], c1[3];
    float w[3][2];
#pragma unroll
    for (int d = 0; d < 3; d++) {
        float coord = xv[d] * fres;
        float cf    = floorf(coord);
        float lc    = coord - cf;
        int   ci    = (int)cf;
        w[d][0] = 1.0f - lc;
        w[d][1] = lc;
        int a = ci % res; if (a < 0) a += res;
        c0[d] = a;
        int b = a + 1;    if (b == res) b = 0;
        c1[d] = b;
    }

    float acc0, acc1;

    if (level < N_DENSE) {
        // ---- dense path: 4 paired loads (z-pairs) ----
        const float4* base = g_dense + p.dense_base[level];
        int rr = res;
        int i00 = (c0[0] * rr + c0[1]) * rr + c0[2];
        int i01 = (c0[0] * rr + c1[1]) * rr + c0[2];
        int i10 = (c1[0] * rr + c0[1]) * rr + c0[2];
        int i11 = (c1[0] * rr + c1[1]) * rr + c0[2];
        float4 f00 = __ldg(base + i00);
        float4 f01 = __ldg(base + i01);
        float4 f10 = __ldg(base + i10);
        float4 f11 = __ldg(base + i11);

        float w00 = w[0][0] * w[1][0];
        float w01 = w[0][0] * w[1][1];
        float w10 = w[0][1] * w[1][0];
        float w11 = w[0][1] * w[1][1];
        float wz0 = w[2][0], wz1 = w[2][1];

        acc0 = w00 * (wz0 * f00.x + wz1 * f00.z)
             + w01 * (wz0 * f01.x + wz1 * f01.z)
             + w10 * (wz0 * f10.x + wz1 * f10.z)
             + w11 * (wz0 * f11.x + wz1 * f11.z);
        acc1 = w00 * (wz0 * f00.y + wz1 * f00.w)
             + w01 * (wz0 * f01.y + wz1 * f01.w)
             + w10 * (wz0 * f10.y + wz1 * f10.w)
             + w11 * (wz0 * f11.y + wz1 * f11.w);
    } else {
        // ---- hashed path: 8 independent gathers ----
        unsigned hp[3][2];
        const unsigned primes[3] = {1u, 2654435761u, 805459861u};
#pragma unroll
        for (int d = 0; d < 3; d++) {
            hp[d][0] = hash_part(c0[d], fres, primes[d]);
            hp[d][1] = hash_part(c1[d], fres, primes[d]);
        }
        const float2* tab = reinterpret_cast<const float2*>(tables)
                            + (size_t)level * TABLE_SIZE;
        unsigned h[8];
#pragma unroll
        for (int k = 0; k < 8; k++) {
            int o0 = (k >> 2) & 1, o1 = (k >> 1) & 1, o2 = k & 1;
            h[k] = (hp[0][o0] + hp[1][o1] + hp[2][o2]) & HASH_MASK;
        }
        float2 f[8];
#pragma unroll
        for (int k = 0; k < 8; k++) f[k] = __ldg(tab + h[k]);

        acc0 = 0.0f; acc1 = 0.0f;
#pragma unroll
        for (int k = 0; k < 8; k++) {
            int o0 = (k >> 2) & 1, o1 = (k >> 1) & 1, o2 = k & 1;
            float wk = w[0][o0] * w[1][o1] * w[2][o2];
            acc0 += wk * f[k].x;
            acc1 += wk * f[k].y;
        }
    }

    reinterpret_cast<float2*>(out)[(size_t)n * N_LEVELS + level] =
        make_float2(acc0, acc1);
}

extern "C" void kernel_launch(void* const* d_in, const int* in_sizes, int n_in,
                              void* d_out, int out_size)
{
    const float* x      = (const float*)d_in[0];
    const float* tables = (const float*)d_in[1];
    float*       out    = (float*)d_out;

    int n_points = in_sizes[0] / 3;

    // Replicate CPython: int(MIN_RES * (MAX_RES/MIN_RES) ** (i/(L-1))) with
    // host libm pow (same as the reference container); e.g. 32^(9/15) lands
    // just below 8.0 in double -> res can be 127, not 128.
    Params p;
    for (int i = 0; i < N_LEVELS; i++) {
        double r = 16.0 * pow(32.0, (double)i / 15.0);
        p.res[i] = (int)r;
    }
    int off = 0;
    p.fill_prefix[0] = 0;
    for (int i = 0; i < N_DENSE; i++) {
        p.dense_base[i] = off;
        int cnt = p.res[i] * p.res[i] * p.res[i];
        off += cnt;
        p.fill_prefix[i + 1] = p.fill_prefix[i] + cnt;
    }
    // off <= DENSE_CAP by construction of the bound

    int total_fill = p.fill_prefix[N_DENSE];
    int threads = 256;
    fill_dense_kernel<<<(total_fill + threads - 1) / threads, threads>>>(
        tables, p, total_fill);

    int total = n_points * N_LEVELS;
    hash_encoding_kernel<<<(total + threads - 1) / threads, threads>>>(
        x, tables, out, p, n_points);
}

// round 4
// speedup vs baseline: 1.1437x; 1.0055x over previous
#include <cuda_runtime.h>
#include <cuda_bf16.h>
#include <math.h>
#include <stdint.h>

#define N_LEVELS   16
#define N_DENSE    10          // levels 0..9 served from dense z-paired grid
#define HASH_BITS  19
#define TABLE_SIZE (1u << HASH_BITS)
#define HASH_MASK  (TABLE_SIZE - 1u)
#define PRIME3     805459861u

// Dense z-paired scratch: entry (cx,cy,cz) = {tab[h(..,cz)], tab[h(..,(cz+1)%res)]}
#define DENSE_CAP  4300000
__device__ float4 g_dense[DENSE_CAP];          // ~68.8 MB static scratch

// z-paired HASH tables for pow2-res hashed levels (12: res 256, 15: res 512)
// TZ[slot][s] = { tab[s], tab[(s + D) & MASK] },  D = prime3 * (2^17/res)
#define MAX_PAIRED 2
__device__ float4 g_ztab[MAX_PAIRED * TABLE_SIZE];   // 16.8 MB

struct Params {
    int res[N_LEVELS];
    int dense_base[N_DENSE];
    int fill_prefix[N_DENSE + 1];
    unsigned pair_mask;               // bit l set -> level l uses g_ztab
    int      pair_slot[N_LEVELS];     // level -> slot in g_ztab
    int      slot_level[MAX_PAIRED];  // slot -> level (for fill)
    unsigned slot_delta[MAX_PAIRED];  // slot -> D
    int      n_paired;
};

// XLA-GPU lowers f32 divide to div.full.f32 (approx, ~2ulp). The hash trunc
// amplifies 1-ulp differences into wrong indices; reproduce the instruction.
__device__ __forceinline__ float div_full(float a, float b) {
    float r;
    asm("div.full.f32 %0, %1, %2;" : "=f"(r) : "f"(a), "f"(b));
    return r;
}

__device__ __forceinline__ unsigned hash_part(int c, float fres, unsigned prime) {
    float cfrac = div_full((float)c, fres);
    float qf = __fmul_rn(__fmul_rn(__fadd_rn(cfrac, 1.0f), 0.5f), 262144.0f);
    unsigned q = (unsigned)qf;           // positive -> trunc == astype(int64)
    return q * prime;                     // uint32 wrap OK: 2^19 | 2^32
}

// ---------------------------------------------------------------------------
// Fill dense grid (levels 0..N_DENSE-1): one thread per corner.
// ---------------------------------------------------------------------------
__global__ void __launch_bounds__(256)
fill_dense_kernel(const float* __restrict__ tables, Params p, int total)
{
    int tid = blockIdx.x * blockDim.x + threadIdx.x;
    if (tid >= total) return;

    int level = 0;
#pragma unroll
    for (int i = 0; i < N_DENSE; i++)
        if (tid >= p.fill_prefix[i + 1]) level = i + 1;

    int r   = tid - p.fill_prefix[level];
    int res = p.res[level];
    int cz = r % res;
    int t  = r / res;
    int cy = t % res;
    int cx = t / res;

    float fres = (float)res;
    unsigned h = (hash_part(cx, fres, 1u) +
                  hash_part(cy, fres, 2654435761u) +
                  hash_part(cz, fres, PRIME3)) & HASH_MASK;

    const float2* tab = reinterpret_cast<const float2*>(tables)
                        + (size_t)level * TABLE_SIZE;
    float2 v = __ldg(tab + h);

    float4* base = g_dense + p.dense_base[level];
    int idx      = (cx * res + cy) * res + cz;
    int idx_prev = (cx * res + cy) * res + (cz == 0 ? res - 1 : cz - 1);

    reinterpret_cast<float2*>(&base[idx])[0]      = v;  // .xy (own z)
    reinterpret_cast<float2*>(&base[idx_prev])[1] = v;  // .zw of z-1 (wrap)
}

// ---------------------------------------------------------------------------
// Fill z-paired hash tables for pow2-res hashed levels. Fully coalesced.
// ---------------------------------------------------------------------------
__global__ void __launch_bounds__(256)
fill_ztab_kernel(const float* __restrict__ tables, Params p, int total)
{
    int tid = blockIdx.x * blockDim.x + threadIdx.x;
    if (tid >= total) return;
    int slot   = tid >> HASH_BITS;
    unsigned s = tid & HASH_MASK;
    int level  = p.slot_level[slot];
    unsigned D = p.slot_delta[slot];

    const float2* tab = reinterpret_cast<const float2*>(tables)
                        + (size_t)level * TABLE_SIZE;
    float2 a = __ldg(tab + s);
    float2 b = __ldg(tab + ((s + D) & HASH_MASK));
    g_ztab[((size_t)slot << HASH_BITS) + s] = make_float4(a.x, a.y, b.x, b.y);
}

// ---------------------------------------------------------------------------
// Main kernel: thread per (point, level), level fastest within warp.
// ---------------------------------------------------------------------------
__global__ void __launch_bounds__(256)
hash_encoding_kernel(const float* __restrict__ x,
                     const float* __restrict__ tables,
                     float* __restrict__ out,
                     Params p,
                     int n_points)
{
    int tid = blockIdx.x * blockDim.x + threadIdx.x;
    int n     = tid >> 4;
    int level = tid & 15;
    if (n >= n_points) return;

    // Cooperative x load: warp covers points n0, n0+1 -> 24B contiguous.
    int lane = threadIdx.x & 31;
    int n0   = (tid & ~31) >> 4;               // first point of this warp
    float2 v = make_float2(0.f, 0.f);
    if (lane < 3) v = *reinterpret_cast<const float2*>(x + (size_t)n0 * 3 + 2 * lane);
    float2 v0 = make_float2(__shfl_sync(0xFFFFFFFFu, v.x, 0), __shfl_sync(0xFFFFFFFFu, v.y, 0));
    float2 v1 = make_float2(__shfl_sync(0xFFFFFFFFu, v.x, 1), __shfl_sync(0xFFFFFFFFu, v.y, 1));
    float2 v2 = make_float2(__shfl_sync(0xFFFFFFFFu, v.x, 2), __shfl_sync(0xFFFFFFFFu, v.y, 2));
    int pn = (tid >> 4) & 1;                    // point parity within warp
    float xv[3];
    xv[0] = pn ? v1.y : v0.x;
    xv[1] = pn ? v2.x : v0.y;
    xv[2] = pn ? v2.y : v1.x;
#pragma unroll
    for (int d = 0; d < 3; d++) xv[d] = fminf(fmaxf(xv[d], -1.0f), 1.0f);

    const int   res  = p.res[level];
    const float fres = (float)res;

    int   c0[3], c1[3];
    float w[3][2];
#pragma unroll
    for (int d = 0; d < 3; d++) {
        float coord = xv[d] * fres;
        float cf    = floorf(coord);
        float lc    = coord - cf;
        int   ci    = (int)cf;
        w[d][0] = 1.0f - lc;
        w[d][1] = lc;
        int a = ci % res; if (a < 0) a += res;
        c0[d] = a;
        int b = a + 1;    if (b == res) b = 0;
        c1[d] = b;
    }

    float w00 = w[0][0] * w[1][0];
    float w01 = w[0][0] * w[1][1];
    float w10 = w[0][1] * w[1][0];
    float w11 = w[0][1] * w[1][1];
    float wz0 = w[2][0], wz1 = w[2][1];

    float acc0, acc1;

    if (level < N_DENSE) {
        // ---- dense path: 4 z-paired LDG.128 ----
        const float4* base = g_dense + p.dense_base[level];
        int rr = res;
        float4 f00 = __ldg(base + (c0[0] * rr + c0[1]) * rr + c0[2]);
        float4 f01 = __ldg(base + (c0[0] * rr + c1[1]) * rr + c0[2]);
        float4 f10 = __ldg(base + (c1[0] * rr + c0[1]) * rr + c0[2]);
        float4 f11 = __ldg(base + (c1[0] * rr + c1[1]) * rr + c0[2]);

        acc0 = w00 * (wz0 * f00.x + wz1 * f00.z)
             + w01 * (wz0 * f01.x + wz1 * f01.z)
             + w10 * (wz0 * f10.x + wz1 * f10.z)
             + w11 * (wz0 * f11.x + wz1 * f11.z);
        acc1 = w00 * (wz0 * f00.y + wz1 * f00.w)
             + w01 * (wz0 * f01.y + wz1 * f01.w)
             + w10 * (wz0 * f10.y + wz1 * f10.w)
             + w11 * (wz0 * f11.y + wz1 * f11.w);
    } else {
        unsigned hp[3][2];
        const unsigned primes[3] = {1u, 2654435761u, PRIME3};
#pragma unroll
        for (int d = 0; d < 3; d++) {
            hp[d][0] = hash_part(c0[d], fres, primes[d]);
            hp[d][1] = hash_part(c1[d], fres, primes[d]);
        }
        const float2* tab = reinterpret_cast<const float2*>(tables)
                            + (size_t)level * TABLE_SIZE;

        if ((p.pair_mask >> level) & 1u) {
            // ---- z-paired hashed path: 4 LDG.128 from g_ztab ----
            const float4* zt = g_ztab + ((size_t)p.pair_slot[level] << HASH_BITS);
            unsigned hz = hp[2][0];
            unsigned s00 = (hp[0][0] + hp[1][0] + hz) & HASH_MASK;
            unsigned s01 = (hp[0][0] + hp[1][1] + hz) & HASH_MASK;
            unsigned s10 = (hp[0][1] + hp[1][0] + hz) & HASH_MASK;
            unsigned s11 = (hp[0][1] + hp[1][1] + hz) & HASH_MASK;
            float4 f00 = __ldg(zt + s00);
            float4 f01 = __ldg(zt + s01);
            float4 f10 = __ldg(zt + s10);
            float4 f11 = __ldg(zt + s11);
            if (c0[2] == res - 1) {
                // wrap: second z-corner is z=0, pair shift invalid -> patch
                unsigned hz1 = hp[2][1];    // hash_part(0) = prime3 * 2^17
                float2 b00 = __ldg(tab + ((hp[0][0] + hp[1][0] + hz1) & HASH_MASK));
                float2 b01 = __ldg(tab + ((hp[0][0] + hp[1][1] + hz1) & HASH_MASK));
                float2 b10 = __ldg(tab + ((hp[0][1] + hp[1][0] + hz1) & HASH_MASK));
                float2 b11 = __ldg(tab + ((hp[0][1] + hp[1][1] + hz1) & HASH_MASK));
                f00.z = b00.x; f00.w = b00.y;
                f01.z = b01.x; f01.w = b01.y;
                f10.z = b10.x; f10.w = b10.y;
                f11.z = b11.x; f11.w = b11.y;
            }
            acc0 = w00 * (wz0 * f00.x + wz1 * f00.z)
                 + w01 * (wz0 * f01.x + wz1 * f01.z)
                 + w10 * (wz0 * f10.x + wz1 * f10.z)
                 + w11 * (wz0 * f11.x + wz1 * f11.z);
            acc1 = w00 * (wz0 * f00.y + wz1 * f00.w)
                 + w01 * (wz0 * f01.y + wz1 * f01.w)
                 + w10 * (wz0 * f10.y + wz1 * f10.w)
                 + w11 * (wz0 * f11.y + wz1 * f11.w);
        } else {
            // ---- general hashed path: 8 independent gathers ----
            unsigned h[8];
#pragma unroll
            for (int k = 0; k < 8; k++) {
                int o0 = (k >> 2) & 1, o1 = (k >> 1) & 1, o2 = k & 1;
                h[k] = (hp[0][o0] + hp[1][o1] + hp[2][o2]) & HASH_MASK;
            }
            float2 f[8];
#pragma unroll
            for (int k = 0; k < 8; k++) f[k] = __ldg(tab + h[k]);

            acc0 = 0.0f; acc1 = 0.0f;
#pragma unroll
            for (int k = 0; k < 8; k++) {
                int o0 = (k >> 2) & 1, o1 = (k >> 1) & 1, o2 = k & 1;
                float wk = w[0][o0] * w[1][o1] * w[2][o2];
                acc0 += wk * f[k].x;
                acc1 += wk * f[k].y;
            }
        }
    }

    reinterpret_cast<float2*>(out)[(size_t)n * N_LEVELS + level] =
        make_float2(acc0, acc1);
}

extern "C" void kernel_launch(void* const* d_in, const int* in_sizes, int n_in,
                              void* d_out, int out_size)
{
    const float* x      = (const float*)d_in[0];
    const float* tables = (const float*)d_in[1];
    float*       out    = (float*)d_out;

    int n_points = in_sizes[0] / 3;

    Params p;
    for (int i = 0; i < N_LEVELS; i++) {
        double r = 16.0 * pow(32.0, (double)i / 15.0);   // host libm pow
        p.res[i] = (int)r;
    }
    int off = 0;
    p.fill_prefix[0] = 0;
    for (int i = 0; i < N_DENSE; i++) {
        p.dense_base[i] = off;
        int cnt = p.res[i] * p.res[i] * p.res[i];
        off += cnt;
        p.fill_prefix[i + 1] = p.fill_prefix[i] + cnt;
    }

    // z-paired hash tables for hashed levels with pow2 res (expect 12, 15)
    p.pair_mask = 0;
    p.n_paired  = 0;
    for (int i = 0; i < N_LEVELS; i++) p.pair_slot[i] = 0;
    for (int lvl = N_DENSE; lvl < N_LEVELS && p.n_paired < MAX_PAIRED; lvl++) {
        int r = p.res[lvl];
        if ((r & (r - 1)) == 0 && r <= 131072) {
            p.pair_mask |= (1u << lvl);
            p.pair_slot[lvl] = p.n_paired;
            p.slot_level[p.n_paired] = lvl;
            p.slot_delta[p.n_paired] = PRIME3 * (131072u / (unsigned)r);
            p.n_paired++;
        }
    }

    int threads = 256;

    int total_fill = p.fill_prefix[N_DENSE];
    fill_dense_kernel<<<(total_fill + threads - 1) / threads, threads>>>(
        tables, p, total_fill);

    if (p.n_paired > 0) {
        int total_z = p.n_paired * (int)TABLE_SIZE;
        fill_ztab_kernel<<<(total_z + threads - 1) / threads, threads>>>(
            tables, p, total_z);
    }

    int total = n_points * N_LEVELS;
    hash_encoding_kernel<<<(total + threads - 1) / threads, threads>>>(
        x, tables, out, p, n_points);
}